// round 1
// baseline (speedup 1.0000x reference)
#include <cuda_runtime.h>
#include <math.h>

#define C_DIM   768
#define NCLS    200
#define BATCH   16
#define M_ROWS  (BATCH * 784)   // 12544
#define FF_ELEMS (BATCH * 64 * 768)              // 786432
#define IMG_OUT_ELEMS (BATCH * 3 * 224 * 224)    // 2408448

// ---------------- scratch (device globals; no runtime alloc allowed) -------
__device__ float g_maxprob[M_ROWS];
__device__ int   g_sel[BATCH];
__device__ float g_A[3][BATCH * 64 * C_DIM];   // outl / outm / outs, [m=b*64+p][c]

// ===========================================================================
// Kernel 1: logits = x @ W_fc^T + b_fc ; maxprob = 1/sum(exp(l - lmax))
// M=12544, N=200, K=768.  BM=64 rows/block, all 200 cols in-block.
// 256 threads = 8 warps; warp w owns rows [8w,8w+8); lane owns cols lane+32j.
// ===========================================================================
#define K1_BM 64
#define K1_BK 16
#define WSS   225   // padded stride for ws (odd -> conflict-free stores)

__global__ __launch_bounds__(256, 2)
void fc_softmax_kernel(const float* __restrict__ x,
                       const float* __restrict__ Wfc,
                       const float* __restrict__ bfc)
{
    __shared__ float xs[K1_BM][K1_BK];
    __shared__ float ws[K1_BK * WSS];

    const int tid  = threadIdx.x;
    const int lane = tid & 31;
    const int warp = tid >> 5;
    const int m0   = blockIdx.x * K1_BM;

    float acc[8][7];
#pragma unroll
    for (int r = 0; r < 8; r++)
#pragma unroll
        for (int j = 0; j < 7; j++) acc[r][j] = 0.f;

    for (int k0 = 0; k0 < C_DIM; k0 += K1_BK) {
        __syncthreads();
        // X tile: 64x16
#pragma unroll
        for (int it = 0; it < 4; it++) {
            int row = (tid >> 4) + it * 16;
            int k   = tid & 15;
            xs[row][k] = x[(size_t)(m0 + row) * C_DIM + k0 + k];
        }
        // W tile transposed into ws[k][n], n padded to 224 with zeros
#pragma unroll
        for (int it = 0; it < 14; it++) {
            int idx = tid + it * 256;
            int k   = idx & 15;
            int n   = idx >> 4;
            ws[k * WSS + n] = (n < NCLS) ? Wfc[(size_t)n * C_DIM + k0 + k] : 0.f;
        }
        __syncthreads();

#pragma unroll
        for (int kk = 0; kk < K1_BK; kk++) {
            float xr[8], wv[7];
#pragma unroll
            for (int r = 0; r < 8; r++) xr[r] = xs[warp * 8 + r][kk];   // broadcast
#pragma unroll
            for (int j = 0; j < 7; j++) wv[j] = ws[kk * WSS + lane + 32 * j];
#pragma unroll
            for (int r = 0; r < 8; r++)
#pragma unroll
                for (int j = 0; j < 7; j++)
                    acc[r][j] = fmaf(xr[r], wv[j], acc[r][j]);
        }
    }

    // bias + per-row max / sum(exp) via warp shuffles
    float bn[7];
#pragma unroll
    for (int j = 0; j < 7; j++) {
        int n = lane + 32 * j;
        bn[j] = (n < NCLS) ? bfc[n] : 0.f;
    }
#pragma unroll
    for (int r = 0; r < 8; r++) {
        float mx = -1e30f;
#pragma unroll
        for (int j = 0; j < 7; j++) {
            int n = lane + 32 * j;
            float l = acc[r][j] + bn[j];
            if (n < NCLS) mx = fmaxf(mx, l);
        }
#pragma unroll
        for (int off = 16; off > 0; off >>= 1)
            mx = fmaxf(mx, __shfl_xor_sync(0xffffffffu, mx, off));
        float s = 0.f;
#pragma unroll
        for (int j = 0; j < 7; j++) {
            int n = lane + 32 * j;
            float l = acc[r][j] + bn[j];
            if (n < NCLS) s += expf(l - mx);
        }
#pragma unroll
        for (int off = 16; off > 0; off >>= 1)
            s += __shfl_xor_sync(0xffffffffu, s, off);
        if (lane == 0) g_maxprob[m0 + warp * 8 + r] = 1.f / s;
    }
}

// ===========================================================================
// Kernel 2: part_logits (8x8 mean-pool, stride 3, pad 2) * mask -> argmax
// ===========================================================================
__global__ void sel_kernel(const float* __restrict__ mask)
{
    int b = blockIdx.x;
    __shared__ float vals[81];
    int p = threadIdx.x;
    if (p < 81) {
        int oy = p / 9, ox = p % 9;
        float s = 0.f;
        for (int i = 0; i < 8; i++) {
            int h = oy * 3 - 2 + i;
            if (h < 0 || h >= 28) continue;
            for (int j = 0; j < 8; j++) {
                int w = ox * 3 - 2 + j;
                if (w < 0 || w >= 28) continue;
                s += g_maxprob[b * 784 + h * 28 + w];
            }
        }
        vals[p] = mask[b * 81 + p] * (s * (1.f / 64.f));
    }
    __syncthreads();
    if (p == 0) {
        float best = vals[0];
        int bi = 0;
        for (int q = 1; q < 81; q++)
            if (vals[q] > best) { best = vals[q]; bi = q; }   // first-index ties
        g_sel[b] = bi;
    }
}

// ===========================================================================
// Kernel 3: gather selected patches from feat (=x reinterpreted [c,28,28]),
// with clamped half-pixel bilinear upsample for the 6x6 and 4x4 patches.
// grid (p=64, b=16, part=3), 256 threads over channels.
// ===========================================================================
__global__ void gather_kernel(const float* __restrict__ x)
{
    int p    = blockIdx.x;
    int b    = blockIdx.y;
    int part = blockIdx.z;
    int sel  = g_sel[b];
    int oy = sel / 9, ox = sel % 9;
    int i = p >> 3, j = p & 7;

    const float* xb = x + (size_t)b * 784 * C_DIM;
    float* out = &g_A[part][(size_t)(b * 64 + p) * C_DIM];

    if (part == 0) {
        int h = oy * 3 - 2 + i, w = ox * 3 - 2 + j;
        bool ok = (h >= 0 && h < 28 && w >= 0 && w < 28);
        const float* src = xb + (size_t)(ok ? (h * 28 + w) : 0) * C_DIM;
        for (int c = threadIdx.x; c < C_DIM; c += blockDim.x)
            out[c] = ok ? src[c] : 0.f;
    } else {
        int   n, basepad;
        float scale, offs;
        if (part == 1) { n = 6; basepad = 1; scale = 0.75f; offs = -0.125f; }
        else           { n = 4; basepad = 0; scale = 0.5f;  offs = -0.25f;  }
        float sy = fminf(fmaxf(scale * i + offs, 0.f), (float)(n - 1));
        float sx = fminf(fmaxf(scale * j + offs, 0.f), (float)(n - 1));
        int iy0 = (int)sy; float fy = sy - iy0; int iy1 = min(iy0 + 1, n - 1);
        int ix0 = (int)sx; float fx = sx - ix0; int ix1 = min(ix0 + 1, n - 1);
        int hb = oy * 3 - basepad, wb = ox * 3 - basepad;
        int h0 = hb + iy0, h1 = hb + iy1, w0 = wb + ix0, w1 = wb + ix1;
        bool okh0 = (h0 >= 0 && h0 < 28), okh1 = (h1 >= 0 && h1 < 28);
        bool okw0 = (w0 >= 0 && w0 < 28), okw1 = (w1 >= 0 && w1 < 28);
        bool ok00 = okh0 && okw0, ok01 = okh0 && okw1;
        bool ok10 = okh1 && okw0, ok11 = okh1 && okw1;
        size_t o00 = (size_t)(ok00 ? (h0 * 28 + w0) : 0) * C_DIM;
        size_t o01 = (size_t)(ok01 ? (h0 * 28 + w1) : 0) * C_DIM;
        size_t o10 = (size_t)(ok10 ? (h1 * 28 + w0) : 0) * C_DIM;
        size_t o11 = (size_t)(ok11 ? (h1 * 28 + w1) : 0) * C_DIM;
        for (int c = threadIdx.x; c < C_DIM; c += blockDim.x) {
            float v00 = ok00 ? xb[o00 + c] : 0.f;
            float v01 = ok01 ? xb[o01 + c] : 0.f;
            float v10 = ok10 ? xb[o10 + c] : 0.f;
            float v11 = ok11 ? xb[o11 + c] : 0.f;
            out[c] = (1.f - fy) * ((1.f - fx) * v00 + fx * v01)
                   +        fy  * ((1.f - fx) * v10 + fx * v11);
        }
    }
}

// ===========================================================================
// Kernel 4: parts GEMM.  C[1024, 768] = [A0@Wl^T | A1@Wm^T | A2@Ws^T] + bias.
// BM=64, BN=64, BK=16; 256 threads, each 4x4.  grid (16, 12).
// ===========================================================================
__global__ __launch_bounds__(256)
void parts_gemm_kernel(const float* __restrict__ Wl, const float* __restrict__ bl,
                       const float* __restrict__ Wm, const float* __restrict__ bm,
                       const float* __restrict__ Ws, const float* __restrict__ bsv,
                       float* __restrict__ out)
{
    const int ny = blockIdx.y;
    int part, noff;
    const float *W, *bias;
    if (ny < 3)      { part = 0; W = Wl; bias = bl;  noff = 0;   }
    else if (ny < 6) { part = 1; W = Wm; bias = bm;  noff = 192; }
    else             { part = 2; W = Ws; bias = bsv; noff = 384; }
    const int n0_cat  = ny * 64;
    const int n0_part = n0_cat - noff;
    const float* A = g_A[part];
    const int m0 = blockIdx.x * 64;

    __shared__ float as[64 * 16];
    __shared__ float bsm[16 * 68];   // padded stride 68 (16B aligned rows)

    const int tid = threadIdx.x;
    const int col_t = tid & 15, row_t = tid >> 4;

    float acc[4][4];
#pragma unroll
    for (int r = 0; r < 4; r++)
#pragma unroll
        for (int c = 0; c < 4; c++) acc[r][c] = 0.f;

    for (int k0 = 0; k0 < C_DIM; k0 += 16) {
        __syncthreads();
#pragma unroll
        for (int it = 0; it < 4; it++) {
            int idx = tid + it * 256;
            int row = idx >> 4, k = idx & 15;
            as[row * 16 + k] = A[(size_t)(m0 + row) * C_DIM + k0 + k];
            bsm[k * 68 + row] = W[(size_t)(n0_part + row) * C_DIM + k0 + k];
        }
        __syncthreads();
#pragma unroll
        for (int kk = 0; kk < 16; kk++) {
            float a[4];
#pragma unroll
            for (int r = 0; r < 4; r++) a[r] = as[(row_t * 4 + r) * 16 + kk];
            float4 bv = *(const float4*)&bsm[kk * 68 + col_t * 4];
            float bb[4] = { bv.x, bv.y, bv.z, bv.w };
#pragma unroll
            for (int r = 0; r < 4; r++)
#pragma unroll
                for (int c = 0; c < 4; c++)
                    acc[r][c] = fmaf(a[r], bb[c], acc[r][c]);
        }
    }

#pragma unroll
    for (int c = 0; c < 4; c++) {
        int npart = n0_part + col_t * 4 + c;
        float bval = bias[npart];
#pragma unroll
        for (int r = 0; r < 4; r++) {
            int m = m0 + row_t * 4 + r;
            out[(size_t)m * 768 + n0_cat + col_t * 4 + c] = acc[r][c] + bval;
        }
    }
}

// ===========================================================================
// Kernel 5: image patch gather (128x128 @ stride 48, pad 32) + bilinear 224.
// ===========================================================================
__global__ void image_kernel(const float* __restrict__ img, float* __restrict__ out)
{
    int idx = blockIdx.x * blockDim.x + threadIdx.x;
    if (idx >= IMG_OUT_ELEMS) return;
    int ox = idx % 224;
    int oy = (idx / 224) % 224;
    int ch = (idx / (224 * 224)) % 3;
    int b  = idx / (3 * 224 * 224);

    int sel = g_sel[b];
    int r0 = (sel / 9) * 48 - 32;
    int c0 = (sel % 9) * 48 - 32;

    const float s = 128.f / 224.f;
    float sy = fminf(fmaxf((oy + 0.5f) * s - 0.5f, 0.f), 127.f);
    float sx = fminf(fmaxf((ox + 0.5f) * s - 0.5f, 0.f), 127.f);
    int py0 = (int)sy; float fy = sy - py0; int py1 = min(py0 + 1, 127);
    int px0 = (int)sx; float fx = sx - px0; int px1 = min(px0 + 1, 127);

    const float* ib = img + (size_t)(b * 3 + ch) * 448 * 448;
    int gy0 = r0 + py0, gy1 = r0 + py1, gx0 = c0 + px0, gx1 = c0 + px1;
    bool oky0 = (gy0 >= 0 && gy0 < 448), oky1 = (gy1 >= 0 && gy1 < 448);
    bool okx0 = (gx0 >= 0 && gx0 < 448), okx1 = (gx1 >= 0 && gx1 < 448);
    float v00 = (oky0 && okx0) ? ib[gy0 * 448 + gx0] : 0.f;
    float v01 = (oky0 && okx1) ? ib[gy0 * 448 + gx1] : 0.f;
    float v10 = (oky1 && okx0) ? ib[gy1 * 448 + gx0] : 0.f;
    float v11 = (oky1 && okx1) ? ib[gy1 * 448 + gx1] : 0.f;

    out[idx] = (1.f - fy) * ((1.f - fx) * v00 + fx * v01)
             +        fy  * ((1.f - fx) * v10 + fx * v11);
}

// ===========================================================================
extern "C" void kernel_launch(void* const* d_in, const int* in_sizes, int n_in,
                              void* d_out, int out_size)
{
    const float* x    = (const float*)d_in[0];
    const float* mask = (const float*)d_in[1];
    const float* img  = (const float*)d_in[2];
    const float* Wfc  = (const float*)d_in[3];
    const float* bfc  = (const float*)d_in[4];
    const float* Wl   = (const float*)d_in[5];
    const float* bl   = (const float*)d_in[6];
    const float* Wm   = (const float*)d_in[7];
    const float* bm   = (const float*)d_in[8];
    const float* Ws   = (const float*)d_in[9];
    const float* bsv  = (const float*)d_in[10];

    float* out_ff  = (float*)d_out;                 // [16,64,768]
    float* out_img = (float*)d_out + FF_ELEMS;      // [16,3,224,224]

    fc_softmax_kernel<<<M_ROWS / K1_BM, 256>>>(x, Wfc, bfc);
    sel_kernel<<<BATCH, 128>>>(mask);
    {
        dim3 g(64, BATCH, 3);
        gather_kernel<<<g, 256>>>(x);
    }
    {
        dim3 g(16, 12);
        parts_gemm_kernel<<<g, 256>>>(Wl, bl, Wm, bm, Ws, bsv, out_ff);
    }
    image_kernel<<<(IMG_OUT_ELEMS + 255) / 256, 256>>>(img, out_img);
}